// round 15
// baseline (speedup 1.0000x reference)
#include <cuda_runtime.h>
#include <cuda_bf16.h>
#include <cstdint>
#include <cstring>

#define NPTS 4096
#define DD   256
#define TSTEPS 8

// -Cy = -log2(e) / (2*rho^2) = -1.4426950408889634/512
#define NEGCY  (-0.0028177637517362566f)
#define TWOCY  (0.005635527503472513f)

// ---------------- scratch (device globals; no allocs allowed) ----------------
__device__ float         g_Z[2][(size_t)NPTS * DD];           // fp32 ping-pong state
__device__ __nv_bfloat16 g_Kbf[(size_t)NPTS * NPTS];          // kernel matrix (upper blocks valid)
__device__ __nv_bfloat16 g_Zbf[(size_t)NPTS * DD];            // bf16 copy of current Z
__device__ __nv_bfloat16 g_Abf[(size_t)TSTEPS * NPTS * DD];   // bf16 A [t][k][n]
__device__ __nv_bfloat16 g_AaffT[(size_t)TSTEPS * DD * DD];   // bf16 Aaff^T [t][e][j]
__device__ float         g_sq[NPTS];                          // = -Cy * ||z||^2 (pre-scaled)
__device__ float         g_P[4][(size_t)NPTS * DD];           // split-K partials (fp32)

// ---------------- PTX helpers ----------------
#define LDSM4(r, addr)                                                        \
    asm volatile("ldmatrix.sync.aligned.m8n8.x4.shared.b16 {%0,%1,%2,%3}, [%4];" \
                 : "=r"((r)[0]), "=r"((r)[1]), "=r"((r)[2]), "=r"((r)[3])     \
                 : "r"(addr))

#define LDSM4T(r, addr)                                                       \
    asm volatile("ldmatrix.sync.aligned.m8n8.x4.trans.shared.b16 {%0,%1,%2,%3}, [%4];" \
                 : "=r"((r)[0]), "=r"((r)[1]), "=r"((r)[2]), "=r"((r)[3])     \
                 : "r"(addr))

#define MMA16816(d, a, b0, b1)                                                \
    asm volatile("mma.sync.aligned.m16n8k16.row.col.f32.bf16.bf16.f32 "       \
                 "{%0,%1,%2,%3}, {%4,%5,%6,%7}, {%8,%9}, {%0,%1,%2,%3};"      \
                 : "+f"((d)[0]), "+f"((d)[1]), "+f"((d)[2]), "+f"((d)[3])     \
                 : "r"((a)[0]), "r"((a)[1]), "r"((a)[2]), "r"((a)[3]),        \
                   "r"(b0), "r"(b1))

#define CP_ASYNC16(dst_u32, src_ptr)                                          \
    asm volatile("cp.async.cg.shared.global [%0], [%1], 16;"                  \
                 :: "r"(dst_u32), "l"(src_ptr) : "memory")

#define CP_COMMIT() asm volatile("cp.async.commit_group;" ::: "memory")
#define CP_WAIT2()  asm volatile("cp.async.wait_group 2;" ::: "memory")
#define CP_WAIT1()  asm volatile("cp.async.wait_group 1;" ::: "memory")
#define CP_WAIT0()  asm volatile("cp.async.wait_group 0;" ::: "memory")

__device__ __forceinline__ uint32_t smem_u32(const void* p) {
    return (uint32_t)__cvta_generic_to_shared(p);
}

__device__ __forceinline__ uint32_t pack_bf16x2(float lo, float hi) {
    __nv_bfloat162 h = __floats2bfloat162_rn(lo, hi);
    uint32_t u;
    memcpy(&u, &h, 4);
    return u;
}

// FFMA-only exp2, degree-4, no clamp (y in [-5, 0] by range analysis).
__device__ __forceinline__ float fexp2(float y) {
    float r = rintf(y);
    float f = y - r;
    float p = 0.0096181291f;
    p = fmaf(p, f, 0.0555041087f);
    p = fmaf(p, f, 0.2402265069f);
    p = fmaf(p, f, 0.6931471806f);
    p = fmaf(p, f, 1.0f);
    return p * __int_as_float(((int)r + 127) << 23);
}

// ---------------- one-time input conversion ----------------
__global__ void k_cvtA(const float* __restrict__ A, __nv_bfloat16* __restrict__ Abf, int n4) {
    int i = blockIdx.x * blockDim.x + threadIdx.x;
    if (i >= n4) return;
    float4 v = ((const float4*)A)[i];
    uint2 u;
    u.x = pack_bf16x2(v.x, v.y);
    u.y = pack_bf16x2(v.z, v.w);
    ((uint2*)Abf)[i] = u;
}

__global__ void k_cvtAaffT(const float* __restrict__ Aaff, __nv_bfloat16* __restrict__ AT) {
    int idx = blockIdx.x * blockDim.x + threadIdx.x;
    if (idx >= TSTEPS * DD * DD) return;
    int t = idx / (DD * DD);
    int rem = idx - t * DD * DD;
    int e = rem / DD;
    int j = rem - e * DD;
    AT[idx] = __float2bfloat16(Aaff[(size_t)t * DD * DD + (size_t)j * DD + e]);
}

// ---------------- prep (used once, before step 0; reads X directly) ----------
__global__ void k_prep(const float* __restrict__ Z, float* __restrict__ sq,
                       __nv_bfloat16* __restrict__ Zbf) {
    int warp = (blockIdx.x * blockDim.x + threadIdx.x) >> 5;
    int lane = threadIdx.x & 31;
    if (warp >= NPTS) return;
    const float4* row = (const float4*)(Z + (size_t)warp * DD);
    float4 v0 = row[lane];
    float4 v1 = row[lane + 32];
    float s = v0.x * v0.x + v0.y * v0.y + v0.z * v0.z + v0.w * v0.w
            + v1.x * v1.x + v1.y * v1.y + v1.z * v1.z + v1.w * v1.w;
    uint2* zb = (uint2*)(Zbf + (size_t)warp * DD);
    uint2 u0, u1;
    u0.x = pack_bf16x2(v0.x, v0.y); u0.y = pack_bf16x2(v0.z, v0.w);
    u1.x = pack_bf16x2(v1.x, v1.y); u1.y = pack_bf16x2(v1.z, v1.w);
    zb[lane] = u0;
    zb[lane + 32] = u1;
#pragma unroll
    for (int o = 16; o > 0; o >>= 1) s += __shfl_xor_sync(0xffffffffu, s, o);
    if (lane == 0) sq[warp] = NEGCY * s;
}

// ---------------- Gram + exp (triangular grid, BK=32, 4-stage pipeline) ------
// BK=32 (8 K-iterations) amortizes pipeline fill best; 4th stage deepens
// prefetch distance to 3 chunks for extra load-latency tolerance.
#define GRAM_STAGE_B 20480
#define GRAM_SMEM    (4 * GRAM_STAGE_B)

__global__ void __launch_bounds__(256, 2)
k_gram(const __nv_bfloat16* __restrict__ Zbf,
       const float* __restrict__ sq,
       __nv_bfloat16* __restrict__ Kout) {
    extern __shared__ char dsm[];
    const uint32_t sb = smem_u32(dsm);

    // triangular decode: blockIdx.x in [0, 528) -> (by, bx) with bx >= by
    int rem = blockIdx.x, by = 0;
    while (rem >= 32 - by) { rem -= 32 - by; by++; }
    const int bx = by + rem;

    const int tid = threadIdx.x;
    const int warp = tid >> 5, lane = tid & 31;
    const int wm = warp & 1, wn = warp >> 1;
    const int i0 = by * 128, j0 = bx * 128;

    float acc[4][4][4];
#pragma unroll
    for (int a = 0; a < 4; a++)
#pragma unroll
        for (int b = 0; b < 4; b++)
#pragma unroll
            for (int c = 0; c < 4; c++) acc[a][b][c] = 0.0f;

    const int r_ld = tid >> 2, g_ld = tid & 3;

#define GRAM_FILL(s, kc)                                                       \
    do {                                                                       \
        uint32_t a_ = sb + (s) * GRAM_STAGE_B;                                 \
        uint32_t b_ = a_ + 10240;                                              \
        CP_ASYNC16(a_ + (r_ld * 40 + g_ld * 8) * 2,                            \
                   Zbf + (size_t)(i0 + r_ld) * DD + (kc) + g_ld * 8);          \
        CP_ASYNC16(a_ + ((r_ld + 64) * 40 + g_ld * 8) * 2,                     \
                   Zbf + (size_t)(i0 + r_ld + 64) * DD + (kc) + g_ld * 8);     \
        CP_ASYNC16(b_ + (r_ld * 40 + g_ld * 8) * 2,                            \
                   Zbf + (size_t)(j0 + r_ld) * DD + (kc) + g_ld * 8);          \
        CP_ASYNC16(b_ + ((r_ld + 64) * 40 + g_ld * 8) * 2,                     \
                   Zbf + (size_t)(j0 + r_ld + 64) * DD + (kc) + g_ld * 8);     \
    } while (0)

    GRAM_FILL(0, 0);
    CP_COMMIT();
    GRAM_FILL(1, 32);
    CP_COMMIT();
    GRAM_FILL(2, 64);
    CP_COMMIT();

    const int nIt = DD / 32;  // 8
    for (int it = 0; it < nIt; it++) {
        if (it + 2 < nIt)      CP_WAIT2();
        else if (it + 1 < nIt) CP_WAIT1();
        else                   CP_WAIT0();
        __syncthreads();
        if (it + 3 < nIt) {
            GRAM_FILL((it + 3) & 3, (it + 3) * 32);
            CP_COMMIT();
        }
        const uint32_t a_ = sb + (it & 3) * GRAM_STAGE_B;
        const uint32_t b_ = a_ + 10240;
#pragma unroll
        for (int kk = 0; kk < 32; kk += 16) {
            uint32_t a[4][4], b[2][4];
#pragma unroll
            for (int mi = 0; mi < 4; mi++)
                LDSM4(a[mi], a_ + ((wm * 64 + mi * 16 + (lane & 15)) * 40
                                   + kk + (lane >> 4) * 8) * 2);
#pragma unroll
            for (int g = 0; g < 2; g++)
                LDSM4(b[g], b_ + ((wn * 32 + g * 16 + (lane & 15)) * 40
                                  + kk + (lane >> 4) * 8) * 2);
#pragma unroll
            for (int mi = 0; mi < 4; mi++)
#pragma unroll
                for (int g = 0; g < 2; g++) {
                    MMA16816(acc[mi][2 * g],     a[mi], b[g][0], b[g][2]);
                    MMA16816(acc[mi][2 * g + 1], a[mi], b[g][1], b[g][3]);
                }
        }
    }
#undef GRAM_FILL

    // epilogue: K = exp2(2Cy*gram + (-Cy*si) + (-Cy*sj)); sq is pre-scaled.
#pragma unroll
    for (int mi = 0; mi < 4; mi++) {
        int row = i0 + wm * 64 + mi * 16 + (lane >> 2);
        float si0 = sq[row];
        float si1 = sq[row + 8];
#pragma unroll
        for (int ni = 0; ni < 4; ni++) {
            int j = j0 + wn * 32 + ni * 8 + 2 * (lane & 3);
            float2 sj = *(const float2*)(sq + j);
            float s00 = si0 + sj.x, s01 = si0 + sj.y;
            float s10 = si1 + sj.x, s11 = si1 + sj.y;
            float k00 = fexp2(fmaf(TWOCY, acc[mi][ni][0], s00));
            float k01 = fexp2(fmaf(TWOCY, acc[mi][ni][1], s01));
            float k10 = fexp2(fmaf(TWOCY, acc[mi][ni][2], s10));
            float k11 = fexp2(fmaf(TWOCY, acc[mi][ni][3], s11));
            *(uint32_t*)(Kout + (size_t)row * NPTS + j)       = pack_bf16x2(k00, k01);
            *(uint32_t*)(Kout + (size_t)(row + 8) * NPTS + j) = pack_bf16x2(k10, k11);
        }
    }
}

// ---------------- step GEMM (split-K=4, symmetric reads, BK=64, 3-stage) -----
#define STEP_STAGE_B 35840
#define STEP_SMEM    (3 * STEP_STAGE_B)

__device__ __forceinline__ void gemm_128x128_sym(
    float (&acc)[4][4][4],
    const __nv_bfloat16* __restrict__ Kbf,
    const __nv_bfloat16* __restrict__ Bp,    // row-major [k][DD]
    int kbeg, int kend,
    int i0, int n0, int tid, int lane, int wm, int wn,
    uint32_t sb, bool sym)
{
    const size_t lda = sym ? (size_t)NPTS : (size_t)DD;

    __syncthreads();  // all warps done with smem from any previous phase

#define STEP_FILL(s, kc)                                                       \
    do {                                                                       \
        uint32_t a_ = sb + (s) * STEP_STAGE_B;                                 \
        uint32_t b_ = a_ + 18432;                                              \
        bool mirror_ = sym && ((kc) < i0);                                     \
        if (!mirror_) {                                                        \
            _Pragma("unroll")                                                  \
            for (int i_ = 0; i_ < 4; i_++) {                                   \
                int idx_ = tid + i_ * 256;                                     \
                int r_ = idx_ >> 3, g_ = idx_ & 7;                             \
                CP_ASYNC16(a_ + (r_ * 72 + g_ * 8) * 2,                        \
                           Kbf + (size_t)(i0 + r_) * lda + (kc) + g_ * 8);     \
            }                                                                  \
        } else {                                                               \
            _Pragma("unroll")                                                  \
            for (int i_ = 0; i_ < 4; i_++) {                                   \
                int idx_ = tid + i_ * 256;                                     \
                int r_ = idx_ >> 4, g_ = idx_ & 15;                            \
                CP_ASYNC16(a_ + (r_ * 136 + g_ * 8) * 2,                       \
                           Kbf + (size_t)((kc) + r_) * NPTS + i0 + g_ * 8);    \
            }                                                                  \
        }                                                                      \
        _Pragma("unroll")                                                      \
        for (int i_ = 0; i_ < 4; i_++) {                                       \
            int idx_ = tid + i_ * 256;                                         \
            int r_ = idx_ >> 4, g_ = idx_ & 15;                                \
            CP_ASYNC16(b_ + (r_ * 136 + g_ * 8) * 2,                           \
                       Bp + (size_t)((kc) + r_) * DD + n0 + g_ * 8);           \
        }                                                                      \
    } while (0)

    const int nIt = (kend - kbeg) / 64;
    STEP_FILL(0, kbeg);
    CP_COMMIT();
    if (nIt > 1) {
        STEP_FILL(1, kbeg + 64);
        CP_COMMIT();
    }

    for (int it = 0; it < nIt; it++) {
        const int kc = kbeg + it * 64;
        const bool mirror = sym && (kc < i0);
        if (it < nIt - 1) CP_WAIT1(); else CP_WAIT0();
        __syncthreads();
        if (it + 2 < nIt) {
            STEP_FILL((it + 2) % 3, kc + 128);
            CP_COMMIT();
        }
        const uint32_t a_ = sb + (it % 3) * STEP_STAGE_B;
        const uint32_t b_ = a_ + 18432;
#pragma unroll
        for (int kk = 0; kk < 64; kk += 16) {
            uint32_t a[4][4], b[2][4];
            if (!mirror) {
#pragma unroll
                for (int mi = 0; mi < 4; mi++)
                    LDSM4(a[mi], a_ + ((wm * 64 + mi * 16 + (lane & 15)) * 72
                                       + kk + (lane >> 4) * 8) * 2);
            } else {
#pragma unroll
                for (int mi = 0; mi < 4; mi++) {
                    uint32_t t[4];
                    LDSM4T(t, a_ + ((kk + (lane & 15)) * 136
                                    + wm * 64 + mi * 16 + (lane >> 4) * 8) * 2);
                    a[mi][0] = t[0]; a[mi][1] = t[2]; a[mi][2] = t[1]; a[mi][3] = t[3];
                }
            }
#pragma unroll
            for (int g = 0; g < 2; g++)
                LDSM4T(b[g], b_ + ((kk + (lane & 15)) * 136
                                   + wn * 32 + g * 16 + (lane >> 4) * 8) * 2);
#pragma unroll
            for (int mi = 0; mi < 4; mi++)
#pragma unroll
                for (int g = 0; g < 2; g++) {
                    MMA16816(acc[mi][2 * g],     a[mi], b[g][0], b[g][1]);
                    MMA16816(acc[mi][2 * g + 1], a[mi], b[g][2], b[g][3]);
                }
        }
    }
#undef STEP_FILL
}

__global__ void __launch_bounds__(256, 2)
k_step(const __nv_bfloat16* __restrict__ Zbf,
       const __nv_bfloat16* __restrict__ Kbf,
       const __nv_bfloat16* __restrict__ Abf,
       const __nv_bfloat16* __restrict__ AaffT,
       float* __restrict__ P) {
    extern __shared__ char dsm[];
    const uint32_t sb = smem_u32(dsm);

    const int tid = threadIdx.x;
    const int warp = tid >> 5, lane = tid & 31;
    const int wm = warp & 1, wn = warp >> 1;
    const int i0 = blockIdx.y * 128, n0 = blockIdx.x * 128;
    const int z = blockIdx.z;
    float* Pout = P + (size_t)z * NPTS * DD;

    float acc[4][4][4];
#pragma unroll
    for (int a = 0; a < 4; a++)
#pragma unroll
        for (int b = 0; b < 4; b++)
#pragma unroll
            for (int c = 0; c < 4; c++) acc[a][b][c] = 0.0f;

    // K @ A over this CTA's K-quarter (1024 deep)
    gemm_128x128_sym(acc, Kbf, Abf, z * (NPTS / 4), (z + 1) * (NPTS / 4),
                     i0, n0, tid, lane, wm, wn, sb, /*sym=*/true);
    // affine term: one 64-deep chunk per split (balanced across z)
    gemm_128x128_sym(acc, Zbf, AaffT, z * 64, (z + 1) * 64,
                     i0, n0, tid, lane, wm, wn, sb, /*sym=*/false);

#pragma unroll
    for (int mi = 0; mi < 4; mi++) {
        int row = i0 + wm * 64 + mi * 16 + (lane >> 2);
#pragma unroll
        for (int ni = 0; ni < 4; ni++) {
            int j = n0 + wn * 32 + ni * 8 + 2 * (lane & 3);
            *(float2*)(Pout + (size_t)row * DD + j)       = make_float2(acc[mi][ni][0], acc[mi][ni][1]);
            *(float2*)(Pout + (size_t)(row + 8) * DD + j) = make_float2(acc[mi][ni][2], acc[mi][ni][3]);
        }
    }
}

// ---------------- combine 4 partials + Euler update + next-step prep ----------
__global__ void k_update(const float* __restrict__ Z,
                         const float* __restrict__ P,
                         const float* __restrict__ baff,
                         float* __restrict__ Znew,
                         __nv_bfloat16* __restrict__ Zbf,
                         float* __restrict__ sq) {
    int row = (blockIdx.x * blockDim.x + threadIdx.x) >> 5;
    int lane = threadIdx.x & 31;
    if (row >= NPTS) return;
    const size_t S4 = (size_t)NPTS * DD / 4;
    const float4* p0r = (const float4*)P + (size_t)row * (DD / 4);
    const float4* zr  = (const float4*)(Z + (size_t)row * DD);
    const float4* br  = (const float4*)baff;
    float4* outr = (float4*)(Znew + (size_t)row * DD);
    uint2* zbr = (uint2*)(Zbf + (size_t)row * DD);
    const float dt = 0.125f;
    float s = 0.0f;
#pragma unroll
    for (int h = 0; h < 2; h++) {
        int idx = lane + h * 32;
        float4 p0 = p0r[idx];
        float4 p1 = p0r[idx + S4];
        float4 p2 = p0r[idx + 2 * S4];
        float4 p3 = p0r[idx + 3 * S4];
        float4 zv = zr[idx], bv = br[idx];
        float4 o;
        o.x = zv.x + dt * (((p0.x + p1.x) + (p2.x + p3.x)) + bv.x);
        o.y = zv.y + dt * (((p0.y + p1.y) + (p2.y + p3.y)) + bv.y);
        o.z = zv.z + dt * (((p0.z + p1.z) + (p2.z + p3.z)) + bv.z);
        o.w = zv.w + dt * (((p0.w + p1.w) + (p2.w + p3.w)) + bv.w);
        outr[idx] = o;
        uint2 u;
        u.x = pack_bf16x2(o.x, o.y);
        u.y = pack_bf16x2(o.z, o.w);
        zbr[idx] = u;
        s += o.x * o.x + o.y * o.y + o.z * o.z + o.w * o.w;
    }
#pragma unroll
    for (int o = 16; o > 0; o >>= 1) s += __shfl_xor_sync(0xffffffffu, s, o);
    if (lane == 0) sq[row] = NEGCY * s;
}

// ---------------- launch ----------------
extern "C" void kernel_launch(void* const* d_in, const int* in_sizes, int n_in,
                              void* d_out, int out_size) {
    const float* X    = (const float*)d_in[0];
    const float* A    = (const float*)d_in[1];
    const float* Aaff = (const float*)d_in[2];
    const float* baff = (const float*)d_in[3];
    float* out = (float*)d_out;

    void* p;
    cudaGetSymbolAddress(&p, g_Z);
    float* Z0 = (float*)p;
    float* Z1 = Z0 + (size_t)NPTS * DD;
    cudaGetSymbolAddress(&p, g_Kbf);   __nv_bfloat16* Kbf   = (__nv_bfloat16*)p;
    cudaGetSymbolAddress(&p, g_Zbf);   __nv_bfloat16* Zbf   = (__nv_bfloat16*)p;
    cudaGetSymbolAddress(&p, g_Abf);   __nv_bfloat16* Abf   = (__nv_bfloat16*)p;
    cudaGetSymbolAddress(&p, g_AaffT); __nv_bfloat16* AaffT = (__nv_bfloat16*)p;
    cudaGetSymbolAddress(&p, g_sq);    float* sqbuf = (float*)p;
    cudaGetSymbolAddress(&p, g_P);     float* Pbuf  = (float*)p;

    cudaFuncSetAttribute(k_gram, cudaFuncAttributeMaxDynamicSharedMemorySize, GRAM_SMEM);
    cudaFuncSetAttribute(k_step, cudaFuncAttributeMaxDynamicSharedMemorySize, STEP_SMEM);

    {
        int n4 = TSTEPS * NPTS * DD / 4;
        k_cvtA<<<(n4 + 255) / 256, 256>>>(A, Abf, n4);
        int nt = TSTEPS * DD * DD;
        k_cvtAaffT<<<(nt + 255) / 256, 256>>>(Aaff, AaffT);
    }

    // step 0 reads X directly (no device-to-device copy needed)
    k_prep<<<NPTS / 8, 256>>>(X, sqbuf, Zbf);

    const float* zcur = X;
    for (int t = 0; t < TSTEPS; t++) {
        float* outp = (t == TSTEPS - 1) ? out : ((t & 1) ? Z1 : Z0);
        k_gram<<<528, 256, GRAM_SMEM>>>(Zbf, sqbuf, Kbf);
        k_step<<<dim3(DD / 128, NPTS / 128, 4), 256, STEP_SMEM>>>(
            Zbf, Kbf,
            Abf + (size_t)t * NPTS * DD,
            AaffT + (size_t)t * DD * DD,
            Pbuf);
        k_update<<<NPTS / 8, 256>>>(zcur, Pbuf, baff + (size_t)t * DD,
                                    outp, Zbf, sqbuf);
        zcur = outp;
    }
}

// round 16
// speedup vs baseline: 1.0109x; 1.0109x over previous
#include <cuda_runtime.h>
#include <cuda_bf16.h>
#include <cstdint>
#include <cstring>

#define NPTS 4096
#define DD   256
#define TSTEPS 8

// -Cy = -log2(e) / (2*rho^2) = -1.4426950408889634/512
#define NEGCY  (-0.0028177637517362566f)
#define TWOCY  (0.005635527503472513f)

// ---------------- scratch (device globals; no allocs allowed) ----------------
__device__ float         g_Z[2][(size_t)NPTS * DD];           // fp32 ping-pong state
__device__ __nv_bfloat16 g_Kbf[(size_t)NPTS * NPTS];          // kernel matrix (upper blocks valid)
__device__ __nv_bfloat16 g_Zbf[(size_t)NPTS * DD];            // bf16 copy of current Z
__device__ __nv_bfloat16 g_Abf[(size_t)TSTEPS * NPTS * DD];   // bf16 A [t][k][n]
__device__ __nv_bfloat16 g_AaffT[(size_t)TSTEPS * DD * DD];   // bf16 Aaff^T [t][e][j]
__device__ float         g_sq[NPTS];                          // = -Cy * ||z||^2 (pre-scaled)
__device__ float         g_P[4][(size_t)NPTS * DD];           // split-K partials (fp32)

// ---------------- PTX helpers ----------------
#define LDSM4(r, addr)                                                        \
    asm volatile("ldmatrix.sync.aligned.m8n8.x4.shared.b16 {%0,%1,%2,%3}, [%4];" \
                 : "=r"((r)[0]), "=r"((r)[1]), "=r"((r)[2]), "=r"((r)[3])     \
                 : "r"(addr))

#define LDSM4T(r, addr)                                                       \
    asm volatile("ldmatrix.sync.aligned.m8n8.x4.trans.shared.b16 {%0,%1,%2,%3}, [%4];" \
                 : "=r"((r)[0]), "=r"((r)[1]), "=r"((r)[2]), "=r"((r)[3])     \
                 : "r"(addr))

#define MMA16816(d, a, b0, b1)                                                \
    asm volatile("mma.sync.aligned.m16n8k16.row.col.f32.bf16.bf16.f32 "       \
                 "{%0,%1,%2,%3}, {%4,%5,%6,%7}, {%8,%9}, {%0,%1,%2,%3};"      \
                 : "+f"((d)[0]), "+f"((d)[1]), "+f"((d)[2]), "+f"((d)[3])     \
                 : "r"((a)[0]), "r"((a)[1]), "r"((a)[2]), "r"((a)[3]),        \
                   "r"(b0), "r"(b1))

#define CP_ASYNC16(dst_u32, src_ptr)                                          \
    asm volatile("cp.async.cg.shared.global [%0], [%1], 16;"                  \
                 :: "r"(dst_u32), "l"(src_ptr) : "memory")

#define CP_COMMIT() asm volatile("cp.async.commit_group;" ::: "memory")
#define CP_WAIT1()  asm volatile("cp.async.wait_group 1;" ::: "memory")
#define CP_WAIT0()  asm volatile("cp.async.wait_group 0;" ::: "memory")

__device__ __forceinline__ uint32_t smem_u32(const void* p) {
    return (uint32_t)__cvta_generic_to_shared(p);
}

__device__ __forceinline__ uint32_t pack_bf16x2(float lo, float hi) {
    __nv_bfloat162 h = __floats2bfloat162_rn(lo, hi);
    uint32_t u;
    memcpy(&u, &h, 4);
    return u;
}

// FFMA-only exp2, degree-4, no clamp (y in [-5, 0] by range analysis).
__device__ __forceinline__ float fexp2(float y) {
    float r = rintf(y);
    float f = y - r;
    float p = 0.0096181291f;
    p = fmaf(p, f, 0.0555041087f);
    p = fmaf(p, f, 0.2402265069f);
    p = fmaf(p, f, 0.6931471806f);
    p = fmaf(p, f, 1.0f);
    return p * __int_as_float(((int)r + 127) << 23);
}

// ---------------- one-time input conversion ----------------
__global__ void k_cvtA(const float* __restrict__ A, __nv_bfloat16* __restrict__ Abf, int n4) {
    int i = blockIdx.x * blockDim.x + threadIdx.x;
    if (i >= n4) return;
    float4 v = ((const float4*)A)[i];
    uint2 u;
    u.x = pack_bf16x2(v.x, v.y);
    u.y = pack_bf16x2(v.z, v.w);
    ((uint2*)Abf)[i] = u;
}

__global__ void k_cvtAaffT(const float* __restrict__ Aaff, __nv_bfloat16* __restrict__ AT) {
    int idx = blockIdx.x * blockDim.x + threadIdx.x;
    if (idx >= TSTEPS * DD * DD) return;
    int t = idx / (DD * DD);
    int rem = idx - t * DD * DD;
    int e = rem / DD;
    int j = rem - e * DD;
    AT[idx] = __float2bfloat16(Aaff[(size_t)t * DD * DD + (size_t)j * DD + e]);
}

// ---------------- prep (used once, before step 0; reads X directly) ----------
__global__ void k_prep(const float* __restrict__ Z, float* __restrict__ sq,
                       __nv_bfloat16* __restrict__ Zbf) {
    int warp = (blockIdx.x * blockDim.x + threadIdx.x) >> 5;
    int lane = threadIdx.x & 31;
    if (warp >= NPTS) return;
    const float4* row = (const float4*)(Z + (size_t)warp * DD);
    float4 v0 = row[lane];
    float4 v1 = row[lane + 32];
    float s = v0.x * v0.x + v0.y * v0.y + v0.z * v0.z + v0.w * v0.w
            + v1.x * v1.x + v1.y * v1.y + v1.z * v1.z + v1.w * v1.w;
    uint2* zb = (uint2*)(Zbf + (size_t)warp * DD);
    uint2 u0, u1;
    u0.x = pack_bf16x2(v0.x, v0.y); u0.y = pack_bf16x2(v0.z, v0.w);
    u1.x = pack_bf16x2(v1.x, v1.y); u1.y = pack_bf16x2(v1.z, v1.w);
    zb[lane] = u0;
    zb[lane + 32] = u1;
#pragma unroll
    for (int o = 16; o > 0; o >>= 1) s += __shfl_xor_sync(0xffffffffu, s, o);
    if (lane == 0) sq[warp] = NEGCY * s;
}

// ---------------- Gram + exp (triangular grid, BK=32, 3-stage pipeline) ------
// Measured optimum: BK=32 (8 K-iterations amortize pipeline fill), 3 stages,
// 128x128 tile, 64x32 warp tile, 2 CTAs/SM.
#define GRAM_STAGE_B 20480
#define GRAM_SMEM    (3 * GRAM_STAGE_B)

__global__ void __launch_bounds__(256, 2)
k_gram(const __nv_bfloat16* __restrict__ Zbf,
       const float* __restrict__ sq,
       __nv_bfloat16* __restrict__ Kout) {
    extern __shared__ char dsm[];
    const uint32_t sb = smem_u32(dsm);

    // triangular decode: blockIdx.x in [0, 528) -> (by, bx) with bx >= by
    int rem = blockIdx.x, by = 0;
    while (rem >= 32 - by) { rem -= 32 - by; by++; }
    const int bx = by + rem;

    const int tid = threadIdx.x;
    const int warp = tid >> 5, lane = tid & 31;
    const int wm = warp & 1, wn = warp >> 1;
    const int i0 = by * 128, j0 = bx * 128;

    float acc[4][4][4];
#pragma unroll
    for (int a = 0; a < 4; a++)
#pragma unroll
        for (int b = 0; b < 4; b++)
#pragma unroll
            for (int c = 0; c < 4; c++) acc[a][b][c] = 0.0f;

    const int r_ld = tid >> 2, g_ld = tid & 3;

#define GRAM_FILL(s, kc)                                                       \
    do {                                                                       \
        uint32_t a_ = sb + (s) * GRAM_STAGE_B;                                 \
        uint32_t b_ = a_ + 10240;                                              \
        CP_ASYNC16(a_ + (r_ld * 40 + g_ld * 8) * 2,                            \
                   Zbf + (size_t)(i0 + r_ld) * DD + (kc) + g_ld * 8);          \
        CP_ASYNC16(a_ + ((r_ld + 64) * 40 + g_ld * 8) * 2,                     \
                   Zbf + (size_t)(i0 + r_ld + 64) * DD + (kc) + g_ld * 8);     \
        CP_ASYNC16(b_ + (r_ld * 40 + g_ld * 8) * 2,                            \
                   Zbf + (size_t)(j0 + r_ld) * DD + (kc) + g_ld * 8);          \
        CP_ASYNC16(b_ + ((r_ld + 64) * 40 + g_ld * 8) * 2,                     \
                   Zbf + (size_t)(j0 + r_ld + 64) * DD + (kc) + g_ld * 8);     \
    } while (0)

    GRAM_FILL(0, 0);
    CP_COMMIT();
    GRAM_FILL(1, 32);
    CP_COMMIT();

    const int nIt = DD / 32;  // 8
    for (int it = 0; it < nIt; it++) {
        if (it < nIt - 1) CP_WAIT1(); else CP_WAIT0();
        __syncthreads();
        if (it + 2 < nIt) {
            GRAM_FILL((it + 2) % 3, (it + 2) * 32);
            CP_COMMIT();
        }
        const uint32_t a_ = sb + (it % 3) * GRAM_STAGE_B;
        const uint32_t b_ = a_ + 10240;
#pragma unroll
        for (int kk = 0; kk < 32; kk += 16) {
            uint32_t a[4][4], b[2][4];
#pragma unroll
            for (int mi = 0; mi < 4; mi++)
                LDSM4(a[mi], a_ + ((wm * 64 + mi * 16 + (lane & 15)) * 40
                                   + kk + (lane >> 4) * 8) * 2);
#pragma unroll
            for (int g = 0; g < 2; g++)
                LDSM4(b[g], b_ + ((wn * 32 + g * 16 + (lane & 15)) * 40
                                  + kk + (lane >> 4) * 8) * 2);
#pragma unroll
            for (int mi = 0; mi < 4; mi++)
#pragma unroll
                for (int g = 0; g < 2; g++) {
                    MMA16816(acc[mi][2 * g],     a[mi], b[g][0], b[g][2]);
                    MMA16816(acc[mi][2 * g + 1], a[mi], b[g][1], b[g][3]);
                }
        }
    }
#undef GRAM_FILL

    // epilogue: K = exp2(2Cy*gram + (-Cy*si) + (-Cy*sj)); sq is pre-scaled.
#pragma unroll
    for (int mi = 0; mi < 4; mi++) {
        int row = i0 + wm * 64 + mi * 16 + (lane >> 2);
        float si0 = sq[row];
        float si1 = sq[row + 8];
#pragma unroll
        for (int ni = 0; ni < 4; ni++) {
            int j = j0 + wn * 32 + ni * 8 + 2 * (lane & 3);
            float2 sj = *(const float2*)(sq + j);
            float s00 = si0 + sj.x, s01 = si0 + sj.y;
            float s10 = si1 + sj.x, s11 = si1 + sj.y;
            float k00 = fexp2(fmaf(TWOCY, acc[mi][ni][0], s00));
            float k01 = fexp2(fmaf(TWOCY, acc[mi][ni][1], s01));
            float k10 = fexp2(fmaf(TWOCY, acc[mi][ni][2], s10));
            float k11 = fexp2(fmaf(TWOCY, acc[mi][ni][3], s11));
            *(uint32_t*)(Kout + (size_t)row * NPTS + j)       = pack_bf16x2(k00, k01);
            *(uint32_t*)(Kout + (size_t)(row + 8) * NPTS + j) = pack_bf16x2(k10, k11);
        }
    }
}

// ---------------- step GEMM (split-K=4, symmetric reads, BK=64, 3-stage) -----
#define STEP_STAGE_B 35840
#define STEP_SMEM    (3 * STEP_STAGE_B)

__device__ __forceinline__ void gemm_128x128_sym(
    float (&acc)[4][4][4],
    const __nv_bfloat16* __restrict__ Kbf,
    const __nv_bfloat16* __restrict__ Bp,    // row-major [k][DD]
    int kbeg, int kend,
    int i0, int n0, int tid, int lane, int wm, int wn,
    uint32_t sb, bool sym)
{
    const size_t lda = sym ? (size_t)NPTS : (size_t)DD;

    __syncthreads();  // all warps done with smem from any previous phase

#define STEP_FILL(s, kc)                                                       \
    do {                                                                       \
        uint32_t a_ = sb + (s) * STEP_STAGE_B;                                 \
        uint32_t b_ = a_ + 18432;                                              \
        bool mirror_ = sym && ((kc) < i0);                                     \
        if (!mirror_) {                                                        \
            _Pragma("unroll")                                                  \
            for (int i_ = 0; i_ < 4; i_++) {                                   \
                int idx_ = tid + i_ * 256;                                     \
                int r_ = idx_ >> 3, g_ = idx_ & 7;                             \
                CP_ASYNC16(a_ + (r_ * 72 + g_ * 8) * 2,                        \
                           Kbf + (size_t)(i0 + r_) * lda + (kc) + g_ * 8);     \
            }                                                                  \
        } else {                                                               \
            _Pragma("unroll")                                                  \
            for (int i_ = 0; i_ < 4; i_++) {                                   \
                int idx_ = tid + i_ * 256;                                     \
                int r_ = idx_ >> 4, g_ = idx_ & 15;                            \
                CP_ASYNC16(a_ + (r_ * 136 + g_ * 8) * 2,                       \
                           Kbf + (size_t)((kc) + r_) * NPTS + i0 + g_ * 8);    \
            }                                                                  \
        }                                                                      \
        _Pragma("unroll")                                                      \
        for (int i_ = 0; i_ < 4; i_++) {                                       \
            int idx_ = tid + i_ * 256;                                         \
            int r_ = idx_ >> 4, g_ = idx_ & 15;                                \
            CP_ASYNC16(b_ + (r_ * 136 + g_ * 8) * 2,                           \
                       Bp + (size_t)((kc) + r_) * DD + n0 + g_ * 8);           \
        }                                                                      \
    } while (0)

    const int nIt = (kend - kbeg) / 64;
    STEP_FILL(0, kbeg);
    CP_COMMIT();
    if (nIt > 1) {
        STEP_FILL(1, kbeg + 64);
        CP_COMMIT();
    }

    for (int it = 0; it < nIt; it++) {
        const int kc = kbeg + it * 64;
        const bool mirror = sym && (kc < i0);
        if (it < nIt - 1) CP_WAIT1(); else CP_WAIT0();
        __syncthreads();
        if (it + 2 < nIt) {
            STEP_FILL((it + 2) % 3, kc + 128);
            CP_COMMIT();
        }
        const uint32_t a_ = sb + (it % 3) * STEP_STAGE_B;
        const uint32_t b_ = a_ + 18432;
#pragma unroll
        for (int kk = 0; kk < 64; kk += 16) {
            uint32_t a[4][4], b[2][4];
            if (!mirror) {
#pragma unroll
                for (int mi = 0; mi < 4; mi++)
                    LDSM4(a[mi], a_ + ((wm * 64 + mi * 16 + (lane & 15)) * 72
                                       + kk + (lane >> 4) * 8) * 2);
            } else {
#pragma unroll
                for (int mi = 0; mi < 4; mi++) {
                    uint32_t t[4];
                    LDSM4T(t, a_ + ((kk + (lane & 15)) * 136
                                    + wm * 64 + mi * 16 + (lane >> 4) * 8) * 2);
                    a[mi][0] = t[0]; a[mi][1] = t[2]; a[mi][2] = t[1]; a[mi][3] = t[3];
                }
            }
#pragma unroll
            for (int g = 0; g < 2; g++)
                LDSM4T(b[g], b_ + ((kk + (lane & 15)) * 136
                                   + wn * 32 + g * 16 + (lane >> 4) * 8) * 2);
#pragma unroll
            for (int mi = 0; mi < 4; mi++)
#pragma unroll
                for (int g = 0; g < 2; g++) {
                    MMA16816(acc[mi][2 * g],     a[mi], b[g][0], b[g][1]);
                    MMA16816(acc[mi][2 * g + 1], a[mi], b[g][2], b[g][3]);
                }
        }
    }
#undef STEP_FILL
}

__global__ void __launch_bounds__(256, 2)
k_step(const __nv_bfloat16* __restrict__ Zbf,
       const __nv_bfloat16* __restrict__ Kbf,
       const __nv_bfloat16* __restrict__ Abf,
       const __nv_bfloat16* __restrict__ AaffT,
       float* __restrict__ P) {
    extern __shared__ char dsm[];
    const uint32_t sb = smem_u32(dsm);

    const int tid = threadIdx.x;
    const int warp = tid >> 5, lane = tid & 31;
    const int wm = warp & 1, wn = warp >> 1;
    const int i0 = blockIdx.y * 128, n0 = blockIdx.x * 128;
    const int z = blockIdx.z;
    float* Pout = P + (size_t)z * NPTS * DD;

    float acc[4][4][4];
#pragma unroll
    for (int a = 0; a < 4; a++)
#pragma unroll
        for (int b = 0; b < 4; b++)
#pragma unroll
            for (int c = 0; c < 4; c++) acc[a][b][c] = 0.0f;

    // K @ A over this CTA's K-quarter (1024 deep)
    gemm_128x128_sym(acc, Kbf, Abf, z * (NPTS / 4), (z + 1) * (NPTS / 4),
                     i0, n0, tid, lane, wm, wn, sb, /*sym=*/true);
    // affine term: one 64-deep chunk per split (balanced across z)
    gemm_128x128_sym(acc, Zbf, AaffT, z * 64, (z + 1) * 64,
                     i0, n0, tid, lane, wm, wn, sb, /*sym=*/false);

#pragma unroll
    for (int mi = 0; mi < 4; mi++) {
        int row = i0 + wm * 64 + mi * 16 + (lane >> 2);
#pragma unroll
        for (int ni = 0; ni < 4; ni++) {
            int j = n0 + wn * 32 + ni * 8 + 2 * (lane & 3);
            *(float2*)(Pout + (size_t)row * DD + j)       = make_float2(acc[mi][ni][0], acc[mi][ni][1]);
            *(float2*)(Pout + (size_t)(row + 8) * DD + j) = make_float2(acc[mi][ni][2], acc[mi][ni][3]);
        }
    }
}

// ---------------- combine 4 partials + Euler update + next-step prep ----------
__global__ void k_update(const float* __restrict__ Z,
                         const float* __restrict__ P,
                         const float* __restrict__ baff,
                         float* __restrict__ Znew,
                         __nv_bfloat16* __restrict__ Zbf,
                         float* __restrict__ sq) {
    int row = (blockIdx.x * blockDim.x + threadIdx.x) >> 5;
    int lane = threadIdx.x & 31;
    if (row >= NPTS) return;
    const size_t S4 = (size_t)NPTS * DD / 4;
    const float4* p0r = (const float4*)P + (size_t)row * (DD / 4);
    const float4* zr  = (const float4*)(Z + (size_t)row * DD);
    const float4* br  = (const float4*)baff;
    float4* outr = (float4*)(Znew + (size_t)row * DD);
    uint2* zbr = (uint2*)(Zbf + (size_t)row * DD);
    const float dt = 0.125f;
    float s = 0.0f;
#pragma unroll
    for (int h = 0; h < 2; h++) {
        int idx = lane + h * 32;
        float4 p0 = p0r[idx];
        float4 p1 = p0r[idx + S4];
        float4 p2 = p0r[idx + 2 * S4];
        float4 p3 = p0r[idx + 3 * S4];
        float4 zv = zr[idx], bv = br[idx];
        float4 o;
        o.x = zv.x + dt * (((p0.x + p1.x) + (p2.x + p3.x)) + bv.x);
        o.y = zv.y + dt * (((p0.y + p1.y) + (p2.y + p3.y)) + bv.y);
        o.z = zv.z + dt * (((p0.z + p1.z) + (p2.z + p3.z)) + bv.z);
        o.w = zv.w + dt * (((p0.w + p1.w) + (p2.w + p3.w)) + bv.w);
        outr[idx] = o;
        uint2 u;
        u.x = pack_bf16x2(o.x, o.y);
        u.y = pack_bf16x2(o.z, o.w);
        zbr[idx] = u;
        s += o.x * o.x + o.y * o.y + o.z * o.z + o.w * o.w;
    }
#pragma unroll
    for (int o = 16; o > 0; o >>= 1) s += __shfl_xor_sync(0xffffffffu, s, o);
    if (lane == 0) sq[row] = NEGCY * s;
}

// ---------------- launch ----------------
extern "C" void kernel_launch(void* const* d_in, const int* in_sizes, int n_in,
                              void* d_out, int out_size) {
    const float* X    = (const float*)d_in[0];
    const float* A    = (const float*)d_in[1];
    const float* Aaff = (const float*)d_in[2];
    const float* baff = (const float*)d_in[3];
    float* out = (float*)d_out;

    void* p;
    cudaGetSymbolAddress(&p, g_Z);
    float* Z0 = (float*)p;
    float* Z1 = Z0 + (size_t)NPTS * DD;
    cudaGetSymbolAddress(&p, g_Kbf);   __nv_bfloat16* Kbf   = (__nv_bfloat16*)p;
    cudaGetSymbolAddress(&p, g_Zbf);   __nv_bfloat16* Zbf   = (__nv_bfloat16*)p;
    cudaGetSymbolAddress(&p, g_Abf);   __nv_bfloat16* Abf   = (__nv_bfloat16*)p;
    cudaGetSymbolAddress(&p, g_AaffT); __nv_bfloat16* AaffT = (__nv_bfloat16*)p;
    cudaGetSymbolAddress(&p, g_sq);    float* sqbuf = (float*)p;
    cudaGetSymbolAddress(&p, g_P);     float* Pbuf  = (float*)p;

    cudaFuncSetAttribute(k_gram, cudaFuncAttributeMaxDynamicSharedMemorySize, GRAM_SMEM);
    cudaFuncSetAttribute(k_step, cudaFuncAttributeMaxDynamicSharedMemorySize, STEP_SMEM);

    {
        int n4 = TSTEPS * NPTS * DD / 4;
        k_cvtA<<<(n4 + 255) / 256, 256>>>(A, Abf, n4);
        int nt = TSTEPS * DD * DD;
        k_cvtAaffT<<<(nt + 255) / 256, 256>>>(Aaff, AaffT);
    }

    // step 0 reads X directly (no device-to-device copy needed)
    k_prep<<<NPTS / 8, 256>>>(X, sqbuf, Zbf);

    const float* zcur = X;
    for (int t = 0; t < TSTEPS; t++) {
        float* outp = (t == TSTEPS - 1) ? out : ((t & 1) ? Z1 : Z0);
        k_gram<<<528, 256, GRAM_SMEM>>>(Zbf, sqbuf, Kbf);
        k_step<<<dim3(DD / 128, NPTS / 128, 4), 256, STEP_SMEM>>>(
            Zbf, Kbf,
            Abf + (size_t)t * NPTS * DD,
            AaffT + (size_t)t * DD * DD,
            Pbuf);
        k_update<<<NPTS / 8, 256>>>(zcur, Pbuf, baff + (size_t)t * DD,
                                    outp, Zbf, sqbuf);
        zcur = outp;
    }
}

// round 17
// speedup vs baseline: 1.0138x; 1.0028x over previous
#include <cuda_runtime.h>
#include <cuda_bf16.h>
#include <cstdint>
#include <cstring>

#define NPTS 4096
#define DD   256
#define TSTEPS 8

// -Cy = -log2(e) / (2*rho^2) = -1.4426950408889634/512
#define NEGCY  (-0.0028177637517362566f)
#define TWOCY  (0.005635527503472513f)

// ---------------- scratch (device globals; no allocs allowed) ----------------
__device__ float         g_Z[2][(size_t)NPTS * DD];           // fp32 ping-pong state
__device__ __nv_bfloat16 g_Kbf[(size_t)NPTS * NPTS];          // kernel matrix (upper blocks valid)
__device__ __nv_bfloat16 g_Zbf[(size_t)NPTS * DD];            // bf16 copy of current Z
__device__ __nv_bfloat16 g_Abf[(size_t)TSTEPS * NPTS * DD];   // bf16 A [t][k][n]
__device__ __nv_bfloat16 g_AaffT[(size_t)TSTEPS * DD * DD];   // bf16 Aaff^T [t][e][j]
__device__ float         g_sq[NPTS];                          // = -Cy * ||z||^2 (pre-scaled)
__device__ float         g_P[4][(size_t)NPTS * DD];           // split-K partials (fp32)

// ---------------- PTX helpers ----------------
#define LDSM4(r, addr)                                                        \
    asm volatile("ldmatrix.sync.aligned.m8n8.x4.shared.b16 {%0,%1,%2,%3}, [%4];" \
                 : "=r"((r)[0]), "=r"((r)[1]), "=r"((r)[2]), "=r"((r)[3])     \
                 : "r"(addr))

#define LDSM4T(r, addr)                                                       \
    asm volatile("ldmatrix.sync.aligned.m8n8.x4.trans.shared.b16 {%0,%1,%2,%3}, [%4];" \
                 : "=r"((r)[0]), "=r"((r)[1]), "=r"((r)[2]), "=r"((r)[3])     \
                 : "r"(addr))

#define MMA16816(d, a, b0, b1)                                                \
    asm volatile("mma.sync.aligned.m16n8k16.row.col.f32.bf16.bf16.f32 "       \
                 "{%0,%1,%2,%3}, {%4,%5,%6,%7}, {%8,%9}, {%0,%1,%2,%3};"      \
                 : "+f"((d)[0]), "+f"((d)[1]), "+f"((d)[2]), "+f"((d)[3])     \
                 : "r"((a)[0]), "r"((a)[1]), "r"((a)[2]), "r"((a)[3]),        \
                   "r"(b0), "r"(b1))

#define CP_ASYNC16(dst_u32, src_ptr)                                          \
    asm volatile("cp.async.cg.shared.global [%0], [%1], 16;"                  \
                 :: "r"(dst_u32), "l"(src_ptr) : "memory")

#define CP_COMMIT() asm volatile("cp.async.commit_group;" ::: "memory")
#define CP_WAIT1()  asm volatile("cp.async.wait_group 1;" ::: "memory")
#define CP_WAIT0()  asm volatile("cp.async.wait_group 0;" ::: "memory")

__device__ __forceinline__ uint32_t smem_u32(const void* p) {
    return (uint32_t)__cvta_generic_to_shared(p);
}

__device__ __forceinline__ uint32_t pack_bf16x2(float lo, float hi) {
    __nv_bfloat162 h = __floats2bfloat162_rn(lo, hi);
    uint32_t u;
    memcpy(&u, &h, 4);
    return u;
}

// FFMA-only exp2, degree-4, no clamp (y in [-5, 0] by range analysis).
__device__ __forceinline__ float fexp2(float y) {
    float r = rintf(y);
    float f = y - r;
    float p = 0.0096181291f;
    p = fmaf(p, f, 0.0555041087f);
    p = fmaf(p, f, 0.2402265069f);
    p = fmaf(p, f, 0.6931471806f);
    p = fmaf(p, f, 1.0f);
    return p * __int_as_float(((int)r + 127) << 23);
}

// ---------------- one-time input conversion ----------------
// A -> bf16, 8 elements per thread, 16B stores.
__global__ void k_cvtA(const float* __restrict__ A, __nv_bfloat16* __restrict__ Abf, int n8) {
    int i = blockIdx.x * blockDim.x + threadIdx.x;
    if (i >= n8) return;
    float4 v0 = ((const float4*)A)[2 * i];
    float4 v1 = ((const float4*)A)[2 * i + 1];
    uint4 u;
    u.x = pack_bf16x2(v0.x, v0.y);
    u.y = pack_bf16x2(v0.z, v0.w);
    u.z = pack_bf16x2(v1.x, v1.y);
    u.w = pack_bf16x2(v1.z, v1.w);
    ((uint4*)Abf)[i] = u;
}

// Tiled transpose + convert: AT[t][e][j] = bf16(Aaff[t][j][e]).
// Coalesced reads (fp32) and coalesced bf16 writes via 32x32 shared tile.
__global__ void k_cvtAaffT(const float* __restrict__ Aaff, __nv_bfloat16* __restrict__ AT) {
    __shared__ float tile[32][33];
    const int t = blockIdx.z;
    const int e0 = blockIdx.x * 32, j0 = blockIdx.y * 32;
    const float* Ap = Aaff + (size_t)t * DD * DD;
    __nv_bfloat16* Tp = AT + (size_t)t * DD * DD;
    const int x = threadIdx.x, y = threadIdx.y;
#pragma unroll
    for (int dy = 0; dy < 32; dy += 8)
        tile[y + dy][x] = Ap[(size_t)(j0 + y + dy) * DD + e0 + x];
    __syncthreads();
#pragma unroll
    for (int dy = 0; dy < 32; dy += 8)
        Tp[(size_t)(e0 + y + dy) * DD + j0 + x] = __float2bfloat16(tile[x][y + dy]);
}

// ---------------- prep (used once, before step 0; reads X directly) ----------
__global__ void k_prep(const float* __restrict__ Z, float* __restrict__ sq,
                       __nv_bfloat16* __restrict__ Zbf) {
    int warp = (blockIdx.x * blockDim.x + threadIdx.x) >> 5;
    int lane = threadIdx.x & 31;
    if (warp >= NPTS) return;
    const float4* row = (const float4*)(Z + (size_t)warp * DD);
    float4 v0 = row[lane];
    float4 v1 = row[lane + 32];
    float s = v0.x * v0.x + v0.y * v0.y + v0.z * v0.z + v0.w * v0.w
            + v1.x * v1.x + v1.y * v1.y + v1.z * v1.z + v1.w * v1.w;
    uint2* zb = (uint2*)(Zbf + (size_t)warp * DD);
    uint2 u0, u1;
    u0.x = pack_bf16x2(v0.x, v0.y); u0.y = pack_bf16x2(v0.z, v0.w);
    u1.x = pack_bf16x2(v1.x, v1.y); u1.y = pack_bf16x2(v1.z, v1.w);
    zb[lane] = u0;
    zb[lane + 32] = u1;
#pragma unroll
    for (int o = 16; o > 0; o >>= 1) s += __shfl_xor_sync(0xffffffffu, s, o);
    if (lane == 0) sq[warp] = NEGCY * s;
}

// ---------------- Gram + exp (triangular grid, BK=32, 3-stage pipeline) ------
// Measured optimum: BK=32 (8 K-iterations amortize pipeline fill), 3 stages,
// 128x128 tile, 64x32 warp tile, 2 CTAs/SM.
#define GRAM_STAGE_B 20480
#define GRAM_SMEM    (3 * GRAM_STAGE_B)

__global__ void __launch_bounds__(256, 2)
k_gram(const __nv_bfloat16* __restrict__ Zbf,
       const float* __restrict__ sq,
       __nv_bfloat16* __restrict__ Kout) {
    extern __shared__ char dsm[];
    const uint32_t sb = smem_u32(dsm);

    // triangular decode: blockIdx.x in [0, 528) -> (by, bx) with bx >= by
    int rem = blockIdx.x, by = 0;
    while (rem >= 32 - by) { rem -= 32 - by; by++; }
    const int bx = by + rem;

    const int tid = threadIdx.x;
    const int warp = tid >> 5, lane = tid & 31;
    const int wm = warp & 1, wn = warp >> 1;
    const int i0 = by * 128, j0 = bx * 128;

    float acc[4][4][4];
#pragma unroll
    for (int a = 0; a < 4; a++)
#pragma unroll
        for (int b = 0; b < 4; b++)
#pragma unroll
            for (int c = 0; c < 4; c++) acc[a][b][c] = 0.0f;

    const int r_ld = tid >> 2, g_ld = tid & 3;

#define GRAM_FILL(s, kc)                                                       \
    do {                                                                       \
        uint32_t a_ = sb + (s) * GRAM_STAGE_B;                                 \
        uint32_t b_ = a_ + 10240;                                              \
        CP_ASYNC16(a_ + (r_ld * 40 + g_ld * 8) * 2,                            \
                   Zbf + (size_t)(i0 + r_ld) * DD + (kc) + g_ld * 8);          \
        CP_ASYNC16(a_ + ((r_ld + 64) * 40 + g_ld * 8) * 2,                     \
                   Zbf + (size_t)(i0 + r_ld + 64) * DD + (kc) + g_ld * 8);     \
        CP_ASYNC16(b_ + (r_ld * 40 + g_ld * 8) * 2,                            \
                   Zbf + (size_t)(j0 + r_ld) * DD + (kc) + g_ld * 8);          \
        CP_ASYNC16(b_ + ((r_ld + 64) * 40 + g_ld * 8) * 2,                     \
                   Zbf + (size_t)(j0 + r_ld + 64) * DD + (kc) + g_ld * 8);     \
    } while (0)

    GRAM_FILL(0, 0);
    CP_COMMIT();
    GRAM_FILL(1, 32);
    CP_COMMIT();

    const int nIt = DD / 32;  // 8
    for (int it = 0; it < nIt; it++) {
        if (it < nIt - 1) CP_WAIT1(); else CP_WAIT0();
        __syncthreads();
        if (it + 2 < nIt) {
            GRAM_FILL((it + 2) % 3, (it + 2) * 32);
            CP_COMMIT();
        }
        const uint32_t a_ = sb + (it % 3) * GRAM_STAGE_B;
        const uint32_t b_ = a_ + 10240;
#pragma unroll
        for (int kk = 0; kk < 32; kk += 16) {
            uint32_t a[4][4], b[2][4];
#pragma unroll
            for (int mi = 0; mi < 4; mi++)
                LDSM4(a[mi], a_ + ((wm * 64 + mi * 16 + (lane & 15)) * 40
                                   + kk + (lane >> 4) * 8) * 2);
#pragma unroll
            for (int g = 0; g < 2; g++)
                LDSM4(b[g], b_ + ((wn * 32 + g * 16 + (lane & 15)) * 40
                                  + kk + (lane >> 4) * 8) * 2);
#pragma unroll
            for (int mi = 0; mi < 4; mi++)
#pragma unroll
                for (int g = 0; g < 2; g++) {
                    MMA16816(acc[mi][2 * g],     a[mi], b[g][0], b[g][2]);
                    MMA16816(acc[mi][2 * g + 1], a[mi], b[g][1], b[g][3]);
                }
        }
    }
#undef GRAM_FILL

    // epilogue: K = exp2(2Cy*gram + (-Cy*si) + (-Cy*sj)); sq is pre-scaled.
#pragma unroll
    for (int mi = 0; mi < 4; mi++) {
        int row = i0 + wm * 64 + mi * 16 + (lane >> 2);
        float si0 = sq[row];
        float si1 = sq[row + 8];
#pragma unroll
        for (int ni = 0; ni < 4; ni++) {
            int j = j0 + wn * 32 + ni * 8 + 2 * (lane & 3);
            float2 sj = *(const float2*)(sq + j);
            float s00 = si0 + sj.x, s01 = si0 + sj.y;
            float s10 = si1 + sj.x, s11 = si1 + sj.y;
            float k00 = fexp2(fmaf(TWOCY, acc[mi][ni][0], s00));
            float k01 = fexp2(fmaf(TWOCY, acc[mi][ni][1], s01));
            float k10 = fexp2(fmaf(TWOCY, acc[mi][ni][2], s10));
            float k11 = fexp2(fmaf(TWOCY, acc[mi][ni][3], s11));
            *(uint32_t*)(Kout + (size_t)row * NPTS + j)       = pack_bf16x2(k00, k01);
            *(uint32_t*)(Kout + (size_t)(row + 8) * NPTS + j) = pack_bf16x2(k10, k11);
        }
    }
}

// ---------------- step GEMM (split-K=4, symmetric reads, BK=64, 3-stage) -----
#define STEP_STAGE_B 35840
#define STEP_SMEM    (3 * STEP_STAGE_B)

__device__ __forceinline__ void gemm_128x128_sym(
    float (&acc)[4][4][4],
    const __nv_bfloat16* __restrict__ Kbf,
    const __nv_bfloat16* __restrict__ Bp,    // row-major [k][DD]
    int kbeg, int kend,
    int i0, int n0, int tid, int lane, int wm, int wn,
    uint32_t sb, bool sym)
{
    const size_t lda = sym ? (size_t)NPTS : (size_t)DD;

    __syncthreads();  // all warps done with smem from any previous phase

#define STEP_FILL(s, kc)                                                       \
    do {                                                                       \
        uint32_t a_ = sb + (s) * STEP_STAGE_B;                                 \
        uint32_t b_ = a_ + 18432;                                              \
        bool mirror_ = sym && ((kc) < i0);                                     \
        if (!mirror_) {                                                        \
            _Pragma("unroll")                                                  \
            for (int i_ = 0; i_ < 4; i_++) {                                   \
                int idx_ = tid + i_ * 256;                                     \
                int r_ = idx_ >> 3, g_ = idx_ & 7;                             \
                CP_ASYNC16(a_ + (r_ * 72 + g_ * 8) * 2,                        \
                           Kbf + (size_t)(i0 + r_) * lda + (kc) + g_ * 8);     \
            }                                                                  \
        } else {                                                               \
            _Pragma("unroll")                                                  \
            for (int i_ = 0; i_ < 4; i_++) {                                   \
                int idx_ = tid + i_ * 256;                                     \
                int r_ = idx_ >> 4, g_ = idx_ & 15;                            \
                CP_ASYNC16(a_ + (r_ * 136 + g_ * 8) * 2,                       \
                           Kbf + (size_t)((kc) + r_) * NPTS + i0 + g_ * 8);    \
            }                                                                  \
        }                                                                      \
        _Pragma("unroll")                                                      \
        for (int i_ = 0; i_ < 4; i_++) {                                       \
            int idx_ = tid + i_ * 256;                                         \
            int r_ = idx_ >> 4, g_ = idx_ & 15;                                \
            CP_ASYNC16(b_ + (r_ * 136 + g_ * 8) * 2,                           \
                       Bp + (size_t)((kc) + r_) * DD + n0 + g_ * 8);           \
        }                                                                      \
    } while (0)

    const int nIt = (kend - kbeg) / 64;
    STEP_FILL(0, kbeg);
    CP_COMMIT();
    if (nIt > 1) {
        STEP_FILL(1, kbeg + 64);
        CP_COMMIT();
    }

    for (int it = 0; it < nIt; it++) {
        const int kc = kbeg + it * 64;
        const bool mirror = sym && (kc < i0);
        if (it < nIt - 1) CP_WAIT1(); else CP_WAIT0();
        __syncthreads();
        if (it + 2 < nIt) {
            STEP_FILL((it + 2) % 3, kc + 128);
            CP_COMMIT();
        }
        const uint32_t a_ = sb + (it % 3) * STEP_STAGE_B;
        const uint32_t b_ = a_ + 18432;
#pragma unroll
        for (int kk = 0; kk < 64; kk += 16) {
            uint32_t a[4][4], b[2][4];
            if (!mirror) {
#pragma unroll
                for (int mi = 0; mi < 4; mi++)
                    LDSM4(a[mi], a_ + ((wm * 64 + mi * 16 + (lane & 15)) * 72
                                       + kk + (lane >> 4) * 8) * 2);
            } else {
#pragma unroll
                for (int mi = 0; mi < 4; mi++) {
                    uint32_t t[4];
                    LDSM4T(t, a_ + ((kk + (lane & 15)) * 136
                                    + wm * 64 + mi * 16 + (lane >> 4) * 8) * 2);
                    a[mi][0] = t[0]; a[mi][1] = t[2]; a[mi][2] = t[1]; a[mi][3] = t[3];
                }
            }
#pragma unroll
            for (int g = 0; g < 2; g++)
                LDSM4T(b[g], b_ + ((kk + (lane & 15)) * 136
                                   + wn * 32 + g * 16 + (lane >> 4) * 8) * 2);
#pragma unroll
            for (int mi = 0; mi < 4; mi++)
#pragma unroll
                for (int g = 0; g < 2; g++) {
                    MMA16816(acc[mi][2 * g],     a[mi], b[g][0], b[g][1]);
                    MMA16816(acc[mi][2 * g + 1], a[mi], b[g][2], b[g][3]);
                }
        }
    }
#undef STEP_FILL
}

__global__ void __launch_bounds__(256, 2)
k_step(const __nv_bfloat16* __restrict__ Zbf,
       const __nv_bfloat16* __restrict__ Kbf,
       const __nv_bfloat16* __restrict__ Abf,
       const __nv_bfloat16* __restrict__ AaffT,
       float* __restrict__ P) {
    extern __shared__ char dsm[];
    const uint32_t sb = smem_u32(dsm);

    const int tid = threadIdx.x;
    const int warp = tid >> 5, lane = tid & 31;
    const int wm = warp & 1, wn = warp >> 1;
    const int i0 = blockIdx.y * 128, n0 = blockIdx.x * 128;
    const int z = blockIdx.z;
    float* Pout = P + (size_t)z * NPTS * DD;

    float acc[4][4][4];
#pragma unroll
    for (int a = 0; a < 4; a++)
#pragma unroll
        for (int b = 0; b < 4; b++)
#pragma unroll
            for (int c = 0; c < 4; c++) acc[a][b][c] = 0.0f;

    // K @ A over this CTA's K-quarter (1024 deep)
    gemm_128x128_sym(acc, Kbf, Abf, z * (NPTS / 4), (z + 1) * (NPTS / 4),
                     i0, n0, tid, lane, wm, wn, sb, /*sym=*/true);
    // affine term: one 64-deep chunk per split (balanced across z)
    gemm_128x128_sym(acc, Zbf, AaffT, z * 64, (z + 1) * 64,
                     i0, n0, tid, lane, wm, wn, sb, /*sym=*/false);

#pragma unroll
    for (int mi = 0; mi < 4; mi++) {
        int row = i0 + wm * 64 + mi * 16 + (lane >> 2);
#pragma unroll
        for (int ni = 0; ni < 4; ni++) {
            int j = n0 + wn * 32 + ni * 8 + 2 * (lane & 3);
            *(float2*)(Pout + (size_t)row * DD + j)       = make_float2(acc[mi][ni][0], acc[mi][ni][1]);
            *(float2*)(Pout + (size_t)(row + 8) * DD + j) = make_float2(acc[mi][ni][2], acc[mi][ni][3]);
        }
    }
}

// ---------------- combine 4 partials + Euler update + next-step prep ----------
__global__ void k_update(const float* __restrict__ Z,
                         const float* __restrict__ P,
                         const float* __restrict__ baff,
                         float* __restrict__ Znew,
                         __nv_bfloat16* __restrict__ Zbf,
                         float* __restrict__ sq) {
    int row = (blockIdx.x * blockDim.x + threadIdx.x) >> 5;
    int lane = threadIdx.x & 31;
    if (row >= NPTS) return;
    const size_t S4 = (size_t)NPTS * DD / 4;
    const float4* p0r = (const float4*)P + (size_t)row * (DD / 4);
    const float4* zr  = (const float4*)(Z + (size_t)row * DD);
    const float4* br  = (const float4*)baff;
    float4* outr = (float4*)(Znew + (size_t)row * DD);
    uint2* zbr = (uint2*)(Zbf + (size_t)row * DD);
    const float dt = 0.125f;
    float s = 0.0f;
#pragma unroll
    for (int h = 0; h < 2; h++) {
        int idx = lane + h * 32;
        float4 p0 = p0r[idx];
        float4 p1 = p0r[idx + S4];
        float4 p2 = p0r[idx + 2 * S4];
        float4 p3 = p0r[idx + 3 * S4];
        float4 zv = zr[idx], bv = br[idx];
        float4 o;
        o.x = zv.x + dt * (((p0.x + p1.x) + (p2.x + p3.x)) + bv.x);
        o.y = zv.y + dt * (((p0.y + p1.y) + (p2.y + p3.y)) + bv.y);
        o.z = zv.z + dt * (((p0.z + p1.z) + (p2.z + p3.z)) + bv.z);
        o.w = zv.w + dt * (((p0.w + p1.w) + (p2.w + p3.w)) + bv.w);
        outr[idx] = o;
        uint2 u;
        u.x = pack_bf16x2(o.x, o.y);
        u.y = pack_bf16x2(o.z, o.w);
        zbr[idx] = u;
        s += o.x * o.x + o.y * o.y + o.z * o.z + o.w * o.w;
    }
#pragma unroll
    for (int o = 16; o > 0; o >>= 1) s += __shfl_xor_sync(0xffffffffu, s, o);
    if (lane == 0) sq[row] = NEGCY * s;
}

// ---------------- launch ----------------
extern "C" void kernel_launch(void* const* d_in, const int* in_sizes, int n_in,
                              void* d_out, int out_size) {
    const float* X    = (const float*)d_in[0];
    const float* A    = (const float*)d_in[1];
    const float* Aaff = (const float*)d_in[2];
    const float* baff = (const float*)d_in[3];
    float* out = (float*)d_out;

    void* p;
    cudaGetSymbolAddress(&p, g_Z);
    float* Z0 = (float*)p;
    float* Z1 = Z0 + (size_t)NPTS * DD;
    cudaGetSymbolAddress(&p, g_Kbf);   __nv_bfloat16* Kbf   = (__nv_bfloat16*)p;
    cudaGetSymbolAddress(&p, g_Zbf);   __nv_bfloat16* Zbf   = (__nv_bfloat16*)p;
    cudaGetSymbolAddress(&p, g_Abf);   __nv_bfloat16* Abf   = (__nv_bfloat16*)p;
    cudaGetSymbolAddress(&p, g_AaffT); __nv_bfloat16* AaffT = (__nv_bfloat16*)p;
    cudaGetSymbolAddress(&p, g_sq);    float* sqbuf = (float*)p;
    cudaGetSymbolAddress(&p, g_P);     float* Pbuf  = (float*)p;

    cudaFuncSetAttribute(k_gram, cudaFuncAttributeMaxDynamicSharedMemorySize, GRAM_SMEM);
    cudaFuncSetAttribute(k_step, cudaFuncAttributeMaxDynamicSharedMemorySize, STEP_SMEM);

    {
        int n8 = TSTEPS * NPTS * DD / 8;
        k_cvtA<<<(n8 + 255) / 256, 256>>>(A, Abf, n8);
        k_cvtAaffT<<<dim3(DD / 32, DD / 32, TSTEPS), dim3(32, 8)>>>(Aaff, AaffT);
    }

    // step 0 reads X directly (no device-to-device copy needed)
    k_prep<<<NPTS / 8, 256>>>(X, sqbuf, Zbf);

    const float* zcur = X;
    for (int t = 0; t < TSTEPS; t++) {
        float* outp = (t == TSTEPS - 1) ? out : ((t & 1) ? Z1 : Z0);
        k_gram<<<528, 256, GRAM_SMEM>>>(Zbf, sqbuf, Kbf);
        k_step<<<dim3(DD / 128, NPTS / 128, 4), 256, STEP_SMEM>>>(
            Zbf, Kbf,
            Abf + (size_t)t * NPTS * DD,
            AaffT + (size_t)t * DD * DD,
            Pbuf);
        k_update<<<NPTS / 8, 256>>>(zcur, Pbuf, baff + (size_t)t * DD,
                                    outp, Zbf, sqbuf);
        zcur = outp;
    }
}